// round 7
// baseline (speedup 1.0000x reference)
#include <cuda_runtime.h>
#include <math.h>
#include <stdint.h>

// Problem constants
#define NB   2
#define NS   1024
#define ND   1024
#define NH   16
#define NDH  64
#define NL   12
#define NHID 2816
#define NV   50257
#define MTOK 2048   // NB*NS

// GEMM tiling: 128x128 block, BK=32, 8 warps (4m x 2n), warp tile 32x64
#define BM 128
#define BN 128
#define BK 32
// smem per buffer: Ah 8KB | Al 8KB | Bh 16KB | Bl 16KB = 48KB? no: 8+8+8+8=32KB
#define SM_AH 0
#define SM_AL 8192
#define SM_BH 16384
#define SM_BL 24576
#define SM_BUF 32768
#define SM_TOT (2 * SM_BUF)

// ---------------- scratch buffers ----------------
__device__ float g_x[MTOK * ND];
__device__ float g_h[MTOK * ND];
__device__ float g_qkv[MTOK * 3 * ND];
__device__ float g_y[MTOK * ND];
__device__ float g_gate[MTOK * NHID];

// ---------------- helpers ----------------
// A tile smem: 128 rows x 32 bf16 (64B/row), chunk-swizzled for LDSM
__device__ __forceinline__ uint32_t a_off(int m, int k) {
    uint32_t chunk = (((uint32_t)(k >> 3)) ^ (((uint32_t)m >> 1) & 3u)) & 3u;
    return (uint32_t)m * 64u + chunk * 16u + (uint32_t)(k & 7) * 2u;
}
// B tile smem: 32 rows x 128 bf16 (256B/row), chunk-swizzled for LDSM.trans
__device__ __forceinline__ uint32_t b_off(int k, int n) {
    uint32_t nb = (uint32_t)(n >> 3);
    uint32_t chunk = (nb & 8u) | ((nb ^ ((uint32_t)k & 7u)) & 7u);
    return (uint32_t)k * 256u + chunk * 16u + (uint32_t)(n & 7) * 2u;
}

__device__ __forceinline__ void ldsm4(uint32_t* r, uint32_t addr) {
    asm volatile("ldmatrix.sync.aligned.m8n8.x4.shared.b16 {%0,%1,%2,%3}, [%4];"
        : "=r"(r[0]), "=r"(r[1]), "=r"(r[2]), "=r"(r[3]) : "r"(addr));
}
__device__ __forceinline__ void ldsm4t(uint32_t* r, uint32_t addr) {
    asm volatile("ldmatrix.sync.aligned.m8n8.x4.trans.shared.b16 {%0,%1,%2,%3}, [%4];"
        : "=r"(r[0]), "=r"(r[1]), "=r"(r[2]), "=r"(r[3]) : "r"(addr));
}
#define MMA_BF16(acc, a, b0, b1)                                              \
    asm volatile(                                                              \
        "mma.sync.aligned.m16n8k16.row.col.f32.bf16.bf16.f32 "                 \
        "{%0,%1,%2,%3}, {%4,%5,%6,%7}, {%8,%9}, {%0,%1,%2,%3};"                \
        : "+f"(acc[0]), "+f"(acc[1]), "+f"(acc[2]), "+f"(acc[3])               \
        : "r"(a[0]), "r"(a[1]), "r"(a[2]), "r"(a[3]), "r"(b0), "r"(b1))

// split float4 into bf16x4 hi (rn) + lo (rn of residual)
__device__ __forceinline__ void split4(float4 v, uint2& hi, uint2& lo) {
    uint32_t h0, h1, l0, l1;
    asm("cvt.rn.bf16x2.f32 %0, %1, %2;" : "=r"(h0) : "f"(v.y), "f"(v.x));
    asm("cvt.rn.bf16x2.f32 %0, %1, %2;" : "=r"(h1) : "f"(v.w), "f"(v.z));
    float hx = __uint_as_float(h0 << 16);
    float hy = __uint_as_float(h0 & 0xffff0000u);
    float hz = __uint_as_float(h1 << 16);
    float hw = __uint_as_float(h1 & 0xffff0000u);
    float lx = v.x - hx, ly = v.y - hy, lz = v.z - hz, lw = v.w - hw;
    asm("cvt.rn.bf16x2.f32 %0, %1, %2;" : "=r"(l0) : "f"(ly), "f"(lx));
    asm("cvt.rn.bf16x2.f32 %0, %1, %2;" : "=r"(l1) : "f"(lw), "f"(lz));
    hi.x = h0; hi.y = h1; lo.x = l0; lo.y = l1;
}

// ---------------- embedding ----------------
__global__ void embed_kernel(const int* __restrict__ idx,
                             const float* __restrict__ wte,
                             const float* __restrict__ wpe,
                             float* __restrict__ x) {
    int row = blockIdx.x;
    int t = threadIdx.x;
    int tok = idx[row];
    int spos = row & (NS - 1);
    float4 a = ((const float4*)(wte + (size_t)tok * ND))[t];
    float4 b = ((const float4*)(wpe + (size_t)spos * ND))[t];
    float4 o;
    o.x = a.x + b.x; o.y = a.y + b.y; o.z = a.z + b.z; o.w = a.w + b.w;
    ((float4*)(x + (size_t)row * ND))[t] = o;
}

// ---------------- rmsnorm ----------------
__global__ void rmsnorm_kernel(const float* __restrict__ in,
                               const float* __restrict__ gamma,
                               float* __restrict__ out) {
    int row = blockIdx.x;
    int t = threadIdx.x;
    float4 v = ((const float4*)(in + (size_t)row * ND))[t];
    float ss = v.x * v.x + v.y * v.y + v.z * v.z + v.w * v.w;
    #pragma unroll
    for (int off = 16; off; off >>= 1)
        ss += __shfl_xor_sync(0xFFFFFFFFu, ss, off);
    __shared__ float red[8];
    if ((t & 31) == 0) red[t >> 5] = ss;
    __syncthreads();
    float tot = red[0] + red[1] + red[2] + red[3] +
                red[4] + red[5] + red[6] + red[7];
    float r = rsqrtf(tot * (1.0f / (float)ND) + 1e-12f);
    float4 g = ((const float4*)gamma)[t];
    float4 o;
    o.x = v.x * r * g.x; o.y = v.y * r * g.y;
    o.z = v.z * r * g.z; o.w = v.w * r * g.w;
    ((float4*)(out + (size_t)row * ND))[t] = o;
}

// ---------------- bf16-split tensor-core GEMM, BK=32, fused epilogues ------
// C[M,N] = epi(A[M,K] @ B[K,N]);  EPI 0: acc; 1: X+acc; 2: silu(X)*acc
template<int EPI, bool NG>
__global__ __launch_bounds__(256, 2)
void gemm_bf(const float* __restrict__ A, const float* __restrict__ B,
             const float* __restrict__ X, float* __restrict__ C,
             int M, int N, int K) {
    extern __shared__ __align__(16) char sm[];
    const uint32_t sb = (uint32_t)__cvta_generic_to_shared(sm);

    const int tid  = threadIdx.x;
    const int lane = tid & 31;
    const int warp = tid >> 5;
    const int wm = warp & 3;        // 0..3
    const int wn = warp >> 2;       // 0..1
    const int lq = lane >> 2;       // 0..7
    const int lr = lane & 3;        // 0..3
    const int m0 = blockIdx.y * BM;
    const int n0 = blockIdx.x * BN;

    float c[2][8][4];
    #pragma unroll
    for (int i = 0; i < 2; i++)
        #pragma unroll
        for (int j = 0; j < 8; j++)
            #pragma unroll
            for (int k = 0; k < 4; k++) c[i][j][k] = 0.0f;

    // gmem indexing: A 128x32 -> 1024 float4, 4/thread: m=li>>3, k0=(li&7)*4
    //                B 32x128 -> 1024 float4, 4/thread: k=li>>5, nb=(li&31)*4
    float4 aS[4], bS[4];

    auto gloadA = [&](int kt) {
        const int kbase = kt * BK;
        #pragma unroll
        for (int i = 0; i < 4; i++) {
            int li = tid + i * 256;
            int m = li >> 3, k0 = (li & 7) * 4;
            aS[i] = *(const float4*)(A + (size_t)(m0 + m) * K + kbase + k0);
        }
    };
    auto gloadB = [&](int kt) {
        const int kbase = kt * BK;
        #pragma unroll
        for (int i = 0; i < 4; i++) {
            int li = tid + i * 256;
            int k = li >> 5, nb = (li & 31) * 4;
            if (!NG) {
                bS[i] = *(const float4*)(B + (size_t)(kbase + k) * N + n0 + nb);
            } else {
                const float* bp = B + (size_t)(kbase + k) * N;
                int n = n0 + nb;
                float t0 = (n + 0 < N) ? bp[n + 0] : 0.0f;
                float t1 = (n + 1 < N) ? bp[n + 1] : 0.0f;
                float t2 = (n + 2 < N) ? bp[n + 2] : 0.0f;
                float t3 = (n + 3 < N) ? bp[n + 3] : 0.0f;
                bS[i] = make_float4(t0, t1, t2, t3);
            }
        }
    };
    auto sstoreA = [&](int buf) {
        char* base = sm + buf * SM_BUF;
        #pragma unroll
        for (int i = 0; i < 4; i++) {
            int li = tid + i * 256;
            int m = li >> 3, k0 = (li & 7) * 4;
            uint2 hi, lo;
            split4(aS[i], hi, lo);
            uint32_t off = a_off(m, k0);
            *(uint2*)(base + SM_AH + off) = hi;
            *(uint2*)(base + SM_AL + off) = lo;
        }
    };
    auto sstoreB = [&](int buf) {
        char* base = sm + buf * SM_BUF;
        #pragma unroll
        for (int i = 0; i < 4; i++) {
            int li = tid + i * 256;
            int k = li >> 5, nb = (li & 31) * 4;
            uint2 hi, lo;
            split4(bS[i], hi, lo);
            uint32_t off = b_off(k, nb);
            *(uint2*)(base + SM_BH + off) = hi;
            *(uint2*)(base + SM_BL + off) = lo;
        }
    };

    const int lid8 = lane >> 3;      // matrix id 0..3
    const int lrow = lane & 7;       // row within matrix

    auto compute = [&](int buf, int kh) {
        const uint32_t bufb = sb + (uint32_t)buf * SM_BUF;
        const uint32_t ah_base = bufb + SM_AH;
        const uint32_t al_base = bufb + SM_AL;
        const uint32_t bh_base = bufb + SM_BH;
        const uint32_t bl_base = bufb + SM_BL;
        const int kb = kh * 16;

        uint32_t ah[2][4], al[2][4];
        {
            int m = ((lid8 & 1) << 3) + lrow;
            int k = kb + ((lid8 >> 1) << 3);
            #pragma unroll
            for (int mf = 0; mf < 2; mf++) {
                uint32_t off = a_off(wm * 32 + mf * 16 + m, k);
                ldsm4(ah[mf], ah_base + off);
                ldsm4(al[mf], al_base + off);
            }
        }
        #pragma unroll
        for (int h = 0; h < 2; h++) {
            uint32_t bhf[4][2], blf[4][2];
            #pragma unroll
            for (int j = 0; j < 2; j++) {
                int k  = kb + ((lid8 & 1) << 3) + lrow;
                int nb = wn * 8 + h * 4 + j * 2 + (lid8 >> 1);
                uint32_t off = b_off(k, nb << 3);
                uint32_t rr[4];
                ldsm4t(rr, bh_base + off);
                bhf[j * 2][0] = rr[0]; bhf[j * 2][1] = rr[1];
                bhf[j * 2 + 1][0] = rr[2]; bhf[j * 2 + 1][1] = rr[3];
                ldsm4t(rr, bl_base + off);
                blf[j * 2][0] = rr[0]; blf[j * 2][1] = rr[1];
                blf[j * 2 + 1][0] = rr[2]; blf[j * 2 + 1][1] = rr[3];
            }
            #pragma unroll
            for (int mf = 0; mf < 2; mf++)
                #pragma unroll
                for (int j = 0; j < 4; j++) {
                    int nf = h * 4 + j;
                    MMA_BF16(c[mf][nf], ah[mf], bhf[j][0], bhf[j][1]);
                    MMA_BF16(c[mf][nf], ah[mf], blf[j][0], blf[j][1]);
                    MMA_BF16(c[mf][nf], al[mf], bhf[j][0], bhf[j][1]);
                }
        }
    };

    // ---- main loop ----
    const int ntk = K / BK;
    gloadA(0); gloadB(0);
    sstoreA(0); sstoreB(0);
    __syncthreads();
    int cur = 0;
    for (int kt = 0; kt < ntk; kt++) {
        const bool nxt = (kt + 1 < ntk);
        if (nxt) gloadA(kt + 1);
        compute(cur, 0);
        if (nxt) { sstoreA(cur ^ 1); gloadB(kt + 1); }
        compute(cur, 1);
        if (nxt) {
            sstoreB(cur ^ 1);
            __syncthreads();
            cur ^= 1;
        }
    }

    // ---- epilogue ----
    #pragma unroll
    for (int mf = 0; mf < 2; mf++) {
        int r0 = m0 + wm * 32 + mf * 16 + lq;
        int r1 = r0 + 8;
        #pragma unroll
        for (int nf = 0; nf < 8; nf++) {
            int col = n0 + wn * 64 + nf * 8 + 2 * lr;
            if (!NG) {
                size_t o0 = (size_t)r0 * N + col;
                size_t o1 = (size_t)r1 * N + col;
                float2 v0 = make_float2(c[mf][nf][0], c[mf][nf][1]);
                float2 v1 = make_float2(c[mf][nf][2], c[mf][nf][3]);
                if (EPI == 1) {
                    float2 x0 = *(const float2*)(X + o0);
                    float2 x1 = *(const float2*)(X + o1);
                    v0.x += x0.x; v0.y += x0.y; v1.x += x1.x; v1.y += x1.y;
                } else if (EPI == 2) {
                    float2 x0 = *(const float2*)(X + o0);
                    float2 x1 = *(const float2*)(X + o1);
                    v0.x *= x0.x / (1.0f + __expf(-x0.x));
                    v0.y *= x0.y / (1.0f + __expf(-x0.y));
                    v1.x *= x1.x / (1.0f + __expf(-x1.x));
                    v1.y *= x1.y / (1.0f + __expf(-x1.y));
                }
                *(float2*)(C + o0) = v0;
                *(float2*)(C + o1) = v1;
            } else {
                #pragma unroll
                for (int e = 0; e < 2; e++) {
                    int n = col + e;
                    if (n < N) {
                        size_t o0 = (size_t)r0 * N + n;
                        size_t o1 = (size_t)r1 * N + n;
                        float v0 = c[mf][nf][e];
                        float v1 = c[mf][nf][2 + e];
                        if (EPI == 1) { v0 += X[o0]; v1 += X[o1]; }
                        else if (EPI == 2) {
                            float x0 = X[o0], x1 = X[o1];
                            v0 *= x0 / (1.0f + __expf(-x0));
                            v1 *= x1 / (1.0f + __expf(-x1));
                        }
                        C[o0] = v0; C[o1] = v1;
                    }
                }
            }
        }
    }
}

// ---------------- flash attention v2 (causal, fp32, 2 threads/row) --------
// grid (NB*NH, NS/64), block 128: 64 q-rows, pair (lane, lane^1) splits dims.
// Dim interleave: thread half h owns dims {i*8 + h*4 .. +3} for i in 0..7.
__global__ __launch_bounds__(128)
void attn_kernel(const float* __restrict__ qkv, float* __restrict__ y) {
    const int bh = blockIdx.x;
    const int b  = bh >> 4;
    const int hh = bh & 15;
    const int qg = blockIdx.y;            // 0..15
    const int tid = threadIdx.x;          // 0..127
    const int row = tid >> 1;             // 0..63
    const int half = tid & 1;
    const int qrow = qg * 64 + row;
    const int doff = half * 4;

    const float* qptr = qkv + ((size_t)(b * NS + qrow) * (3 * ND)) + hh * NDH;
    float4 q[8];
    #pragma unroll
    for (int i = 0; i < 8; i++)
        q[i] = *(const float4*)(qptr + i * 8 + doff);

    float4 o[8];
    #pragma unroll
    for (int i = 0; i < 8; i++) o[i] = make_float4(0.f, 0.f, 0.f, 0.f);
    float m = -1e30f, l = 0.0f;

    __shared__ float ksm[64][64];
    __shared__ float vsm[64][64];

    const int ntiles = qg + 1;
    for (int kt = 0; kt < ntiles; kt++) {
        const int kbase = kt * 64;
        #pragma unroll
        for (int i = 0; i < 8; i++) {
            int li = tid + i * 128;
            int r  = li >> 4;
            int c4 = (li & 15) * 4;
            const float* base = qkv + ((size_t)(b * NS + kbase + r) * (3 * ND))
                                + hh * NDH + c4;
            *(float4*)&ksm[r][c4] = *(const float4*)(base + ND);
            *(float4*)&vsm[r][c4] = *(const float4*)(base + 2 * ND);
        }
        __syncthreads();

        #pragma unroll 1
        for (int jt = 0; jt < 4; jt++) {
            float s[16];
            #pragma unroll
            for (int j = 0; j < 16; j++) {
                int jr = jt * 16 + j;
                float a = 0.0f;
                #pragma unroll
                for (int i = 0; i < 8; i++) {
                    float4 kv = *(const float4*)&ksm[jr][i * 8 + doff];
                    a += q[i].x * kv.x + q[i].y * kv.y
                       + q[i].z * kv.z + q[i].w * kv.w;
                }
                a += __shfl_xor_sync(0xFFFFFFFFu, a, 1);
                int key = kbase + jr;
                s[j] = (key <= qrow) ? a * 0.125f : -1e30f;
            }
            float tm = s[0];
            #pragma unroll
            for (int j = 1; j < 16; j++) tm = fmaxf(tm, s[j]);
            float mnew = fmaxf(m, tm);
            float corr = __expf(m - mnew);
            float psum = 0.0f;
            #pragma unroll
            for (int j = 0; j < 16; j++) {
                s[j] = __expf(s[j] - mnew);
                psum += s[j];
            }
            l = l * corr + psum;
            m = mnew;
            #pragma unroll
            for (int i = 0; i < 8; i++) {
                o[i].x *= corr; o[i].y *= corr; o[i].z *= corr; o[i].w *= corr;
            }
            #pragma unroll
            for (int j = 0; j < 16; j++) {
                float p = s[j];
                int jr = jt * 16 + j;
                #pragma unroll
                for (int i = 0; i < 8; i++) {
                    float4 vv = *(const float4*)&vsm[jr][i * 8 + doff];
                    o[i].x += p * vv.x; o[i].y += p * vv.y;
                    o[i].z += p * vv.z; o[i].w += p * vv.w;
                }
            }
        }
        __syncthreads();
    }

    float inv = 1.0f / l;
    float* yp = y + ((size_t)(b * NS + qrow) * ND) + hh * NDH;
    #pragma unroll
    for (int i = 0; i < 8; i++) {
        float4 st;
        st.x = o[i].x * inv; st.y = o[i].y * inv;
        st.z = o[i].z * inv; st.w = o[i].w * inv;
        *(float4*)(yp + i * 8 + doff) = st;
    }
}

// ---------------- launch ----------------
extern "C" void kernel_launch(void* const* d_in, const int* in_sizes, int n_in,
                              void* d_out, int out_size) {
    const int*   idx   = (const int*)  d_in[0];
    const float* wte   = (const float*)d_in[1];
    const float* wpe   = (const float*)d_in[2];
    const float* g1    = (const float*)d_in[3];
    const float* Wqkv  = (const float*)d_in[4];
    const float* Wproj = (const float*)d_in[5];
    const float* g2    = (const float*)d_in[6];
    const float* Wg    = (const float*)d_in[7];
    const float* Wu    = (const float*)d_in[8];
    const float* Wd    = (const float*)d_in[9];
    const float* gf    = (const float*)d_in[10];
    const float* Wlm   = (const float*)d_in[11];
    float* out = (float*)d_out;

    float *px, *ph, *pqkv, *py, *pg;
    cudaGetSymbolAddress((void**)&px,   g_x);
    cudaGetSymbolAddress((void**)&ph,   g_h);
    cudaGetSymbolAddress((void**)&pqkv, g_qkv);
    cudaGetSymbolAddress((void**)&py,   g_y);
    cudaGetSymbolAddress((void**)&pg,   g_gate);

    cudaFuncSetAttribute(gemm_bf<0, false>,
        cudaFuncAttributeMaxDynamicSharedMemorySize, SM_TOT);
    cudaFuncSetAttribute(gemm_bf<1, false>,
        cudaFuncAttributeMaxDynamicSharedMemorySize, SM_TOT);
    cudaFuncSetAttribute(gemm_bf<2, false>,
        cudaFuncAttributeMaxDynamicSharedMemorySize, SM_TOT);
    cudaFuncSetAttribute(gemm_bf<0, true>,
        cudaFuncAttributeMaxDynamicSharedMemorySize, SM_TOT);

    embed_kernel<<<MTOK, 256>>>(idx, wte, wpe, px);

    for (int l = 0; l < NL; l++) {
        rmsnorm_kernel<<<MTOK, 256>>>(px, g1 + (size_t)l * ND, ph);
        gemm_bf<0, false><<<dim3(3 * ND / BN, MTOK / BM), 256, SM_TOT>>>(
            ph, Wqkv + (size_t)l * ND * 3 * ND, nullptr, pqkv, MTOK, 3 * ND, ND);
        attn_kernel<<<dim3(NB * NH, NS / 64), 128>>>(pqkv, py);
        gemm_bf<1, false><<<dim3(ND / BN, MTOK / BM), 256, SM_TOT>>>(
            py, Wproj + (size_t)l * ND * ND, px, px, MTOK, ND, ND);
        rmsnorm_kernel<<<MTOK, 256>>>(px, g2 + (size_t)l * ND, ph);
        gemm_bf<0, false><<<dim3(NHID / BN, MTOK / BM), 256, SM_TOT>>>(
            ph, Wg + (size_t)l * ND * NHID, nullptr, pg, MTOK, NHID, ND);
        gemm_bf<2, false><<<dim3(NHID / BN, MTOK / BM), 256, SM_TOT>>>(
            ph, Wu + (size_t)l * ND * NHID, pg, pg, MTOK, NHID, ND);
        gemm_bf<1, false><<<dim3(ND / BN, MTOK / BM), 256, SM_TOT>>>(
            pg, Wd + (size_t)l * NHID * ND, px, px, MTOK, ND, NHID);
    }

    rmsnorm_kernel<<<MTOK, 256>>>(px, gf, ph);
    gemm_bf<0, true><<<dim3((NV + BN - 1) / BN, MTOK / BM), 256, SM_TOT>>>(
        ph, Wlm, nullptr, out, MTOK, NV, ND);
}

// round 8
// speedup vs baseline: 1.2919x; 1.2919x over previous
#include <cuda_runtime.h>
#include <math.h>
#include <stdint.h>

// Problem constants
#define NB   2
#define NS   1024
#define ND   1024
#define NH   16
#define NDH  64
#define NL   12
#define NHID 2816
#define NV   50257
#define MTOK 2048   // NB*NS

// GEMM tiling: 128x128 block, BK=16, 8 warps (4m x 2n), warp tile 32x64
#define BM 128
#define BN 128
#define BK 16

// ---------------- scratch buffers ----------------
__device__ float g_x[MTOK * ND];
__device__ float g_h[MTOK * ND];
__device__ float g_qkv[MTOK * 3 * ND];
__device__ float g_y[MTOK * ND];
__device__ float g_gate[MTOK * NHID];

// ---------------- helpers ----------------
// A tile smem: 128 rows x 16 bf16 (32B/row), chunk-swizzled for LDSM
__device__ __forceinline__ uint32_t a_off(int m, int k) {
    uint32_t chunk = ((uint32_t)(k >> 3) ^ ((uint32_t)(m >> 2) & 1u)) & 1u;
    return (uint32_t)m * 32u + chunk * 16u + (uint32_t)(k & 7) * 2u;
}
// B tile smem: 16 rows x 128 bf16 (256B/row), chunk-swizzled for LDSM.trans
__device__ __forceinline__ uint32_t b_off(int k, int n) {
    uint32_t nb = (uint32_t)(n >> 3);
    uint32_t chunk = (nb & 8u) | ((nb ^ ((uint32_t)k & 7u)) & 7u);
    return (uint32_t)k * 256u + chunk * 16u + (uint32_t)(n & 7) * 2u;
}

__device__ __forceinline__ void ldsm4(uint32_t* r, uint32_t addr) {
    asm volatile("ldmatrix.sync.aligned.m8n8.x4.shared.b16 {%0,%1,%2,%3}, [%4];"
        : "=r"(r[0]), "=r"(r[1]), "=r"(r[2]), "=r"(r[3]) : "r"(addr));
}
__device__ __forceinline__ void ldsm4t(uint32_t* r, uint32_t addr) {
    asm volatile("ldmatrix.sync.aligned.m8n8.x4.trans.shared.b16 {%0,%1,%2,%3}, [%4];"
        : "=r"(r[0]), "=r"(r[1]), "=r"(r[2]), "=r"(r[3]) : "r"(addr));
}
#define MMA_BF16(acc, a, b0, b1)                                              \
    asm volatile(                                                              \
        "mma.sync.aligned.m16n8k16.row.col.f32.bf16.bf16.f32 "                 \
        "{%0,%1,%2,%3}, {%4,%5,%6,%7}, {%8,%9}, {%0,%1,%2,%3};"                \
        : "+f"(acc[0]), "+f"(acc[1]), "+f"(acc[2]), "+f"(acc[3])               \
        : "r"(a[0]), "r"(a[1]), "r"(a[2]), "r"(a[3]), "r"(b0), "r"(b1))

// split float4 into bf16x4 hi (rn) + lo (rn of residual)
__device__ __forceinline__ void split4(float4 v, uint2& hi, uint2& lo) {
    uint32_t h0, h1, l0, l1;
    asm("cvt.rn.bf16x2.f32 %0, %1, %2;" : "=r"(h0) : "f"(v.y), "f"(v.x));
    asm("cvt.rn.bf16x2.f32 %0, %1, %2;" : "=r"(h1) : "f"(v.w), "f"(v.z));
    float hx = __uint_as_float(h0 << 16);
    float hy = __uint_as_float(h0 & 0xffff0000u);
    float hz = __uint_as_float(h1 << 16);
    float hw = __uint_as_float(h1 & 0xffff0000u);
    float lx = v.x - hx, ly = v.y - hy, lz = v.z - hz, lw = v.w - hw;
    asm("cvt.rn.bf16x2.f32 %0, %1, %2;" : "=r"(l0) : "f"(ly), "f"(lx));
    asm("cvt.rn.bf16x2.f32 %0, %1, %2;" : "=r"(l1) : "f"(lw), "f"(lz));
    hi.x = h0; hi.y = h1; lo.x = l0; lo.y = l1;
}

// ---------------- embedding ----------------
__global__ void embed_kernel(const int* __restrict__ idx,
                             const float* __restrict__ wte,
                             const float* __restrict__ wpe,
                             float* __restrict__ x) {
    int row = blockIdx.x;
    int t = threadIdx.x;
    int tok = idx[row];
    int spos = row & (NS - 1);
    float4 a = ((const float4*)(wte + (size_t)tok * ND))[t];
    float4 b = ((const float4*)(wpe + (size_t)spos * ND))[t];
    float4 o;
    o.x = a.x + b.x; o.y = a.y + b.y; o.z = a.z + b.z; o.w = a.w + b.w;
    ((float4*)(x + (size_t)row * ND))[t] = o;
}

// ---------------- rmsnorm ----------------
__global__ void rmsnorm_kernel(const float* __restrict__ in,
                               const float* __restrict__ gamma,
                               float* __restrict__ out) {
    int row = blockIdx.x;
    int t = threadIdx.x;
    float4 v = ((const float4*)(in + (size_t)row * ND))[t];
    float ss = v.x * v.x + v.y * v.y + v.z * v.z + v.w * v.w;
    #pragma unroll
    for (int off = 16; off; off >>= 1)
        ss += __shfl_xor_sync(0xFFFFFFFFu, ss, off);
    __shared__ float red[8];
    if ((t & 31) == 0) red[t >> 5] = ss;
    __syncthreads();
    float tot = red[0] + red[1] + red[2] + red[3] +
                red[4] + red[5] + red[6] + red[7];
    float r = rsqrtf(tot * (1.0f / (float)ND) + 1e-12f);
    float4 g = ((const float4*)gamma)[t];
    float4 o;
    o.x = v.x * r * g.x; o.y = v.y * r * g.y;
    o.z = v.z * r * g.z; o.w = v.w * r * g.w;
    ((float4*)(out + (size_t)row * ND))[t] = o;
}

// ---------------- bf16-split tensor-core GEMM with fused epilogues ----------
// C[M,N] = epi(A[M,K] @ B[K,N]);  EPI 0: acc; 1: X+acc; 2: silu(X)*acc
template<int EPI, bool NG>
__global__ __launch_bounds__(256, 2)
void gemm_bf(const float* __restrict__ A, const float* __restrict__ B,
             const float* __restrict__ X, float* __restrict__ C,
             int M, int N, int K) {
    // per buffer: Ah 4KB | Al 4KB | Bh 4KB | Bl 4KB  -> 16KB; double buffered
    __shared__ __align__(16) char sm[2 * 16384];
    const uint32_t sb = (uint32_t)__cvta_generic_to_shared(sm);

    const int tid  = threadIdx.x;
    const int lane = tid & 31;
    const int warp = tid >> 5;
    const int wm = warp & 3;        // 0..3
    const int wn = warp >> 2;       // 0..1
    const int lq = lane >> 2;       // 0..7
    const int lr = lane & 3;        // 0..3
    const int m0 = blockIdx.y * BM;
    const int n0 = blockIdx.x * BN;

    float c[2][8][4];
    #pragma unroll
    for (int i = 0; i < 2; i++)
        #pragma unroll
        for (int j = 0; j < 8; j++)
            #pragma unroll
            for (int k = 0; k < 4; k++) c[i][j][k] = 0.0f;

    float4 aS[2], bS[2];

    auto gload = [&](int kt) {
        const int kbase = kt * BK;
        #pragma unroll
        for (int i = 0; i < 2; i++) {
            int li = tid + i * 256;
            int m = li >> 2, k0 = (li & 3) * 4;
            aS[i] = *(const float4*)(A + (size_t)(m0 + m) * K + kbase + k0);
        }
        #pragma unroll
        for (int i = 0; i < 2; i++) {
            int li = tid + i * 256;
            int k = li >> 5, nb = (li & 31) * 4;
            if (!NG) {
                bS[i] = *(const float4*)(B + (size_t)(kbase + k) * N + n0 + nb);
            } else {
                const float* bp = B + (size_t)(kbase + k) * N;
                int n = n0 + nb;
                float t0 = (n + 0 < N) ? bp[n + 0] : 0.0f;
                float t1 = (n + 1 < N) ? bp[n + 1] : 0.0f;
                float t2 = (n + 2 < N) ? bp[n + 2] : 0.0f;
                float t3 = (n + 3 < N) ? bp[n + 3] : 0.0f;
                bS[i] = make_float4(t0, t1, t2, t3);
            }
        }
    };

    auto sstore = [&](int buf) {
        char* base = sm + buf * 16384;
        #pragma unroll
        for (int i = 0; i < 2; i++) {
            int li = tid + i * 256;
            int m = li >> 2, k0 = (li & 3) * 4;
            uint2 hi, lo;
            split4(aS[i], hi, lo);
            uint32_t off = a_off(m, k0);
            *(uint2*)(base + off)        = hi;
            *(uint2*)(base + 4096 + off) = lo;
        }
        #pragma unroll
        for (int i = 0; i < 2; i++) {
            int li = tid + i * 256;
            int k = li >> 5, nb = (li & 31) * 4;
            uint2 hi, lo;
            split4(bS[i], hi, lo);
            uint32_t off = b_off(k, nb);
            *(uint2*)(base + 8192 + off)  = hi;
            *(uint2*)(base + 12288 + off) = lo;
        }
    };

    const int lid8 = lane >> 3;      // matrix id 0..3
    const int lrow = lane & 7;       // row within matrix

    auto compute = [&](int buf) {
        const uint32_t ah_base = sb + (uint32_t)buf * 16384u;
        const uint32_t al_base = ah_base + 4096u;
        const uint32_t bh_base = ah_base + 8192u;
        const uint32_t bl_base = ah_base + 12288u;

        uint32_t ah[2][4], al[2][4];
        {
            int m = ((lid8 & 1) << 3) + lrow;
            int k = (lid8 >> 1) << 3;
            #pragma unroll
            for (int mf = 0; mf < 2; mf++) {
                uint32_t off = a_off(wm * 32 + mf * 16 + m, k);
                ldsm4(ah[mf], ah_base + off);
                ldsm4(al[mf], al_base + off);
            }
        }
        #pragma unroll
        for (int h = 0; h < 2; h++) {
            uint32_t bhf[4][2], blf[4][2];
            #pragma unroll
            for (int j = 0; j < 2; j++) {
                int k  = ((lid8 & 1) << 3) + lrow;
                int nb = wn * 8 + h * 4 + j * 2 + (lid8 >> 1);
                uint32_t off = b_off(k, nb << 3);
                uint32_t rr[4];
                ldsm4t(rr, bh_base + off);
                bhf[j * 2][0] = rr[0]; bhf[j * 2][1] = rr[1];
                bhf[j * 2 + 1][0] = rr[2]; bhf[j * 2 + 1][1] = rr[3];
                ldsm4t(rr, bl_base + off);
                blf[j * 2][0] = rr[0]; blf[j * 2][1] = rr[1];
                blf[j * 2 + 1][0] = rr[2]; blf[j * 2 + 1][1] = rr[3];
            }
            #pragma unroll
            for (int mf = 0; mf < 2; mf++)
                #pragma unroll
                for (int j = 0; j < 4; j++) {
                    int nf = h * 4 + j;
                    MMA_BF16(c[mf][nf], ah[mf], bhf[j][0], bhf[j][1]);
                    MMA_BF16(c[mf][nf], ah[mf], blf[j][0], blf[j][1]);
                    MMA_BF16(c[mf][nf], al[mf], bhf[j][0], bhf[j][1]);
                }
        }
    };

    // ---- main loop ----
    const int ntk = K / BK;
    gload(0);
    sstore(0);
    __syncthreads();
    int cur = 0;
    for (int kt = 0; kt < ntk; kt++) {
        if (kt + 1 < ntk) gload(kt + 1);
        compute(cur);
        if (kt + 1 < ntk) {
            sstore(cur ^ 1);
            __syncthreads();
            cur ^= 1;
        }
    }

    // ---- epilogue ----
    #pragma unroll
    for (int mf = 0; mf < 2; mf++) {
        int r0 = m0 + wm * 32 + mf * 16 + lq;
        int r1 = r0 + 8;
        #pragma unroll
        for (int nf = 0; nf < 8; nf++) {
            int col = n0 + wn * 64 + nf * 8 + 2 * lr;
            if (!NG) {
                size_t o0 = (size_t)r0 * N + col;
                size_t o1 = (size_t)r1 * N + col;
                float2 v0 = make_float2(c[mf][nf][0], c[mf][nf][1]);
                float2 v1 = make_float2(c[mf][nf][2], c[mf][nf][3]);
                if (EPI == 1) {
                    float2 x0 = *(const float2*)(X + o0);
                    float2 x1 = *(const float2*)(X + o1);
                    v0.x += x0.x; v0.y += x0.y; v1.x += x1.x; v1.y += x1.y;
                } else if (EPI == 2) {
                    float2 x0 = *(const float2*)(X + o0);
                    float2 x1 = *(const float2*)(X + o1);
                    v0.x *= x0.x / (1.0f + __expf(-x0.x));
                    v0.y *= x0.y / (1.0f + __expf(-x0.y));
                    v1.x *= x1.x / (1.0f + __expf(-x1.x));
                    v1.y *= x1.y / (1.0f + __expf(-x1.y));
                }
                *(float2*)(C + o0) = v0;
                *(float2*)(C + o1) = v1;
            } else {
                #pragma unroll
                for (int e = 0; e < 2; e++) {
                    int n = col + e;
                    if (n < N) {
                        size_t o0 = (size_t)r0 * N + n;
                        size_t o1 = (size_t)r1 * N + n;
                        float v0 = c[mf][nf][e];
                        float v1 = c[mf][nf][2 + e];
                        if (EPI == 1) { v0 += X[o0]; v1 += X[o1]; }
                        else if (EPI == 2) {
                            float x0 = X[o0], x1 = X[o1];
                            v0 *= x0 / (1.0f + __expf(-x0));
                            v1 *= x1 / (1.0f + __expf(-x1));
                        }
                        C[o0] = v0; C[o1] = v1;
                    }
                }
            }
        }
    }
}

// ---------------- flash attention v2 (causal, fp32, 2 threads/row) --------
// grid (NB*NH, NS/64), block 128: 64 q-rows, pair (lane, lane^1) splits dims.
__global__ __launch_bounds__(128)
void attn_kernel(const float* __restrict__ qkv, float* __restrict__ y) {
    const int bh = blockIdx.x;
    const int b  = bh >> 4;
    const int hh = bh & 15;
    const int qg = blockIdx.y;            // 0..15
    const int tid = threadIdx.x;          // 0..127
    const int row = tid >> 1;             // 0..63
    const int half = tid & 1;
    const int qrow = qg * 64 + row;
    const int doff = half * 4;

    const float* qptr = qkv + ((size_t)(b * NS + qrow) * (3 * ND)) + hh * NDH;
    float4 q[8];
    #pragma unroll
    for (int i = 0; i < 8; i++)
        q[i] = *(const float4*)(qptr + i * 8 + doff);

    float4 o[8];
    #pragma unroll
    for (int i = 0; i < 8; i++) o[i] = make_float4(0.f, 0.f, 0.f, 0.f);
    float m = -1e30f, l = 0.0f;

    __shared__ float ksm[64][64];
    __shared__ float vsm[64][64];

    const int ntiles = qg + 1;
    for (int kt = 0; kt < ntiles; kt++) {
        const int kbase = kt * 64;
        #pragma unroll
        for (int i = 0; i < 8; i++) {
            int li = tid + i * 128;
            int r  = li >> 4;
            int c4 = (li & 15) * 4;
            const float* base = qkv + ((size_t)(b * NS + kbase + r) * (3 * ND))
                                + hh * NDH + c4;
            *(float4*)&ksm[r][c4] = *(const float4*)(base + ND);
            *(float4*)&vsm[r][c4] = *(const float4*)(base + 2 * ND);
        }
        __syncthreads();

        #pragma unroll 1
        for (int jt = 0; jt < 4; jt++) {
            float s[16];
            #pragma unroll
            for (int j = 0; j < 16; j++) {
                int jr = jt * 16 + j;
                float a = 0.0f;
                #pragma unroll
                for (int i = 0; i < 8; i++) {
                    float4 kv = *(const float4*)&ksm[jr][i * 8 + doff];
                    a += q[i].x * kv.x + q[i].y * kv.y
                       + q[i].z * kv.z + q[i].w * kv.w;
                }
                a += __shfl_xor_sync(0xFFFFFFFFu, a, 1);
                int key = kbase + jr;
                s[j] = (key <= qrow) ? a * 0.125f : -1e30f;
            }
            float tm = s[0];
            #pragma unroll
            for (int j = 1; j < 16; j++) tm = fmaxf(tm, s[j]);
            float mnew = fmaxf(m, tm);
            float corr = __expf(m - mnew);
            float psum = 0.0f;
            #pragma unroll
            for (int j = 0; j < 16; j++) {
                s[j] = __expf(s[j] - mnew);
                psum += s[j];
            }
            l = l * corr + psum;
            m = mnew;
            #pragma unroll
            for (int i = 0; i < 8; i++) {
                o[i].x *= corr; o[i].y *= corr; o[i].z *= corr; o[i].w *= corr;
            }
            #pragma unroll
            for (int j = 0; j < 16; j++) {
                float p = s[j];
                int jr = jt * 16 + j;
                #pragma unroll
                for (int i = 0; i < 8; i++) {
                    float4 vv = *(const float4*)&vsm[jr][i * 8 + doff];
                    o[i].x += p * vv.x; o[i].y += p * vv.y;
                    o[i].z += p * vv.z; o[i].w += p * vv.w;
                }
            }
        }
        __syncthreads();
    }

    float inv = 1.0f / l;
    float* yp = y + ((size_t)(b * NS + qrow) * ND) + hh * NDH;
    #pragma unroll
    for (int i = 0; i < 8; i++) {
        float4 st;
        st.x = o[i].x * inv; st.y = o[i].y * inv;
        st.z = o[i].z * inv; st.w = o[i].w * inv;
        *(float4*)(yp + i * 8 + doff) = st;
    }
}

// ---------------- launch ----------------
extern "C" void kernel_launch(void* const* d_in, const int* in_sizes, int n_in,
                              void* d_out, int out_size) {
    const int*   idx   = (const int*)  d_in[0];
    const float* wte   = (const float*)d_in[1];
    const float* wpe   = (const float*)d_in[2];
    const float* g1    = (const float*)d_in[3];
    const float* Wqkv  = (const float*)d_in[4];
    const float* Wproj = (const float*)d_in[5];
    const float* g2    = (const float*)d_in[6];
    const float* Wg    = (const float*)d_in[7];
    const float* Wu    = (const float*)d_in[8];
    const float* Wd    = (const float*)d_in[9];
    const float* gf    = (const float*)d_in[10];
    const float* Wlm   = (const float*)d_in[11];
    float* out = (float*)d_out;

    float *px, *ph, *pqkv, *py, *pg;
    cudaGetSymbolAddress((void**)&px,   g_x);
    cudaGetSymbolAddress((void**)&ph,   g_h);
    cudaGetSymbolAddress((void**)&pqkv, g_qkv);
    cudaGetSymbolAddress((void**)&py,   g_y);
    cudaGetSymbolAddress((void**)&pg,   g_gate);

    embed_kernel<<<MTOK, 256>>>(idx, wte, wpe, px);

    for (int l = 0; l < NL; l++) {
        rmsnorm_kernel<<<MTOK, 256>>>(px, g1 + (size_t)l * ND, ph);
        gemm_bf<0, false><<<dim3(3 * ND / BN, MTOK / BM), 256>>>(
            ph, Wqkv + (size_t)l * ND * 3 * ND, nullptr, pqkv, MTOK, 3 * ND, ND);
        attn_kernel<<<dim3(NB * NH, NS / 64), 128>>>(pqkv, py);
        gemm_bf<1, false><<<dim3(ND / BN, MTOK / BM), 256>>>(
            py, Wproj + (size_t)l * ND * ND, px, px, MTOK, ND, ND);
        rmsnorm_kernel<<<MTOK, 256>>>(px, g2 + (size_t)l * ND, ph);
        gemm_bf<0, false><<<dim3(NHID / BN, MTOK / BM), 256>>>(
            ph, Wg + (size_t)l * ND * NHID, nullptr, pg, MTOK, NHID, ND);
        gemm_bf<2, false><<<dim3(NHID / BN, MTOK / BM), 256>>>(
            ph, Wu + (size_t)l * ND * NHID, pg, pg, MTOK, NHID, ND);
        gemm_bf<1, false><<<dim3(ND / BN, MTOK / BM), 256>>>(
            pg, Wd + (size_t)l * NHID * ND, px, px, MTOK, ND, NHID);
    }

    rmsnorm_kernel<<<MTOK, 256>>>(px, gf, ph);
    gemm_bf<0, true><<<dim3((NV + BN - 1) / BN, MTOK / BM), 256>>>(
        ph, Wlm, nullptr, out, MTOK, NV, ND);
}

// round 10
// speedup vs baseline: 1.3624x; 1.0545x over previous
#include <cuda_runtime.h>
#include <math.h>
#include <stdint.h>

// Problem constants
#define NB_  2
#define NS   1024
#define ND   1024
#define NH   16
#define NDH  64
#define NL   12
#define NHID 2816
#define NV   50257
#define NVP  50304   // padded LM-head N (128*393)
#define MTOK 2048    // NB_*NS

// GEMM tiling: 128x128 block, BK=16, 8 warps (4m x 2n), warp tile 32x64
#define BM 128
#define BN 128
#define BK 16
#define STAGE_BYTES 16384
#define NSTAGE 4
#define SMEM_BYTES (NSTAGE * STAGE_BYTES)

// ---------------- activation scratch ----------------
__device__ float    g_x[MTOK * ND];            // residual (fp32)
__device__ uint16_t g_hh[MTOK * ND];           // rmsnorm out hi
__device__ uint16_t g_hl[MTOK * ND];           // rmsnorm out lo
__device__ float    g_qkv[MTOK * 3 * ND];      // qkv (fp32)
__device__ uint16_t g_yh[MTOK * ND];           // attn out hi
__device__ uint16_t g_yl[MTOK * ND];           // attn out lo
__device__ float    g_gate[MTOK * NHID];       // gate pre-act (fp32)
__device__ uint16_t g_sh[MTOK * NHID];         // swiglu out hi
__device__ uint16_t g_sl[MTOK * NHID];         // swiglu out lo

// ---------------- weight bf16 hi/lo ----------------
__device__ uint16_t g_wqkv_h[NL * ND * 3 * ND];
__device__ uint16_t g_wqkv_l[NL * ND * 3 * ND];
__device__ uint16_t g_wproj_h[NL * ND * ND];
__device__ uint16_t g_wproj_l[NL * ND * ND];
__device__ uint16_t g_wg_h[NL * ND * NHID];
__device__ uint16_t g_wg_l[NL * ND * NHID];
__device__ uint16_t g_wu_h[NL * ND * NHID];
__device__ uint16_t g_wu_l[NL * ND * NHID];
__device__ uint16_t g_wd_h[NL * NHID * ND];
__device__ uint16_t g_wd_l[NL * NHID * ND];
__device__ uint16_t g_wlm_h[ND * NVP];
__device__ uint16_t g_wlm_l[ND * NVP];

// ---------------- helpers ----------------
// A tile smem: 128 rows x 16 bf16 (32B/row), chunk-swizzled for LDSM
__device__ __forceinline__ uint32_t a_off(int m, int k) {
    uint32_t chunk = ((uint32_t)(k >> 3) ^ ((uint32_t)(m >> 2) & 1u)) & 1u;
    return (uint32_t)m * 32u + chunk * 16u + (uint32_t)(k & 7) * 2u;
}
// B tile smem: 16 rows x 128 bf16 (256B/row), chunk-swizzled for LDSM.trans
__device__ __forceinline__ uint32_t b_off(int k, int n) {
    uint32_t nb = (uint32_t)(n >> 3);
    uint32_t chunk = (nb & 8u) | ((nb ^ ((uint32_t)k & 7u)) & 7u);
    return (uint32_t)k * 256u + chunk * 16u + (uint32_t)(n & 7) * 2u;
}

__device__ __forceinline__ void ldsm4(uint32_t* r, uint32_t addr) {
    asm volatile("ldmatrix.sync.aligned.m8n8.x4.shared.b16 {%0,%1,%2,%3}, [%4];"
        : "=r"(r[0]), "=r"(r[1]), "=r"(r[2]), "=r"(r[3]) : "r"(addr));
}
__device__ __forceinline__ void ldsm4t(uint32_t* r, uint32_t addr) {
    asm volatile("ldmatrix.sync.aligned.m8n8.x4.trans.shared.b16 {%0,%1,%2,%3}, [%4];"
        : "=r"(r[0]), "=r"(r[1]), "=r"(r[2]), "=r"(r[3]) : "r"(addr));
}
#define MMA_BF16(acc, a, b0, b1)                                              \
    asm volatile(                                                              \
        "mma.sync.aligned.m16n8k16.row.col.f32.bf16.bf16.f32 "                 \
        "{%0,%1,%2,%3}, {%4,%5,%6,%7}, {%8,%9}, {%0,%1,%2,%3};"                \
        : "+f"(acc[0]), "+f"(acc[1]), "+f"(acc[2]), "+f"(acc[3])               \
        : "r"(a[0]), "r"(a[1]), "r"(a[2]), "r"(a[3]), "r"(b0), "r"(b1))

#define CPASYNC16(dst, src)                                                    \
    asm volatile("cp.async.cg.shared.global [%0], [%1], 16;"                   \
                 :: "r"(dst), "l"(src))

// split float4 into bf16x4 hi (rn) + lo (rn of residual)
__device__ __forceinline__ void split4(float4 v, uint2& hi, uint2& lo) {
    uint32_t h0, h1, l0, l1;
    asm("cvt.rn.bf16x2.f32 %0, %1, %2;" : "=r"(h0) : "f"(v.y), "f"(v.x));
    asm("cvt.rn.bf16x2.f32 %0, %1, %2;" : "=r"(h1) : "f"(v.w), "f"(v.z));
    float hx = __uint_as_float(h0 << 16);
    float hy = __uint_as_float(h0 & 0xffff0000u);
    float hz = __uint_as_float(h1 << 16);
    float hw = __uint_as_float(h1 & 0xffff0000u);
    float lx = v.x - hx, ly = v.y - hy, lz = v.z - hz, lw = v.w - hw;
    asm("cvt.rn.bf16x2.f32 %0, %1, %2;" : "=r"(l0) : "f"(ly), "f"(lx));
    asm("cvt.rn.bf16x2.f32 %0, %1, %2;" : "=r"(l1) : "f"(lw), "f"(lz));
    hi.x = h0; hi.y = h1; lo.x = l0; lo.y = l1;
}
// split pair (a=elem0, b=elem1) into hi/lo bf16x2 words
__device__ __forceinline__ void split2(float a, float b, uint32_t& h, uint32_t& l) {
    asm("cvt.rn.bf16x2.f32 %0, %1, %2;" : "=r"(h) : "f"(b), "f"(a));
    float ha = __uint_as_float(h << 16);
    float hb = __uint_as_float(h & 0xffff0000u);
    asm("cvt.rn.bf16x2.f32 %0, %1, %2;" : "=r"(l) : "f"(b - hb), "f"(a - ha));
}

// ---------------- weight split kernels ----------------
__global__ void wsplit_kernel(const float* __restrict__ w,
                              uint16_t* __restrict__ wh,
                              uint16_t* __restrict__ wl, int n4) {
    int i = blockIdx.x * 256 + threadIdx.x;
    if (i < n4) {
        float4 v = ((const float4*)w)[i];
        uint2 hi, lo;
        split4(v, hi, lo);
        ((uint2*)wh)[i] = hi;
        ((uint2*)wl)[i] = lo;
    }
}
// LM head: pad [1024,50257] -> [1024,50304] with zeros
__global__ void wsplit_pad_kernel(const float* __restrict__ w,
                                  uint16_t* __restrict__ wh,
                                  uint16_t* __restrict__ wl) {
    int c = blockIdx.x * 256 + threadIdx.x;
    int r = blockIdx.y;
    if (c < NVP) {
        float x = (c < NV) ? w[(size_t)r * NV + c] : 0.0f;
        uint32_t h, l;
        split2(x, 0.0f, h, l);
        wh[(size_t)r * NVP + c] = (uint16_t)(h & 0xffffu);
        wl[(size_t)r * NVP + c] = (uint16_t)(l & 0xffffu);
    }
}

// ---------------- embedding ----------------
__global__ void embed_kernel(const int* __restrict__ idx,
                             const float* __restrict__ wte,
                             const float* __restrict__ wpe,
                             float* __restrict__ x) {
    int row = blockIdx.x;
    int t = threadIdx.x;
    int tok = idx[row];
    int spos = row & (NS - 1);
    float4 a = ((const float4*)(wte + (size_t)tok * ND))[t];
    float4 b = ((const float4*)(wpe + (size_t)spos * ND))[t];
    float4 o;
    o.x = a.x + b.x; o.y = a.y + b.y; o.z = a.z + b.z; o.w = a.w + b.w;
    ((float4*)(x + (size_t)row * ND))[t] = o;
}

// ---------------- rmsnorm -> bf16 hi/lo ----------------
__global__ void rmsnorm_hl_kernel(const float* __restrict__ in,
                                  const float* __restrict__ gamma,
                                  uint16_t* __restrict__ oh,
                                  uint16_t* __restrict__ ol) {
    int row = blockIdx.x;
    int t = threadIdx.x;
    float4 v = ((const float4*)(in + (size_t)row * ND))[t];
    float ss = v.x * v.x + v.y * v.y + v.z * v.z + v.w * v.w;
    #pragma unroll
    for (int off = 16; off; off >>= 1)
        ss += __shfl_xor_sync(0xFFFFFFFFu, ss, off);
    __shared__ float red[8];
    if ((t & 31) == 0) red[t >> 5] = ss;
    __syncthreads();
    float tot = red[0] + red[1] + red[2] + red[3] +
                red[4] + red[5] + red[6] + red[7];
    float r = rsqrtf(tot * (1.0f / (float)ND) + 1e-12f);
    float4 g = ((const float4*)gamma)[t];
    float4 o;
    o.x = v.x * r * g.x; o.y = v.y * r * g.y;
    o.z = v.z * r * g.z; o.w = v.w * r * g.w;
    uint2 hi, lo;
    split4(o, hi, lo);
    ((uint2*)oh)[row * 256 + t] = hi;
    ((uint2*)ol)[row * 256 + t] = lo;
}

// ---------------- bf16 tensor-core GEMM, cp.async 4-stage ------------------
// C[M,N] = epi(A[M,K] @ B[K,N]) with A,B given as bf16 hi/lo pairs.
// EPI 0: C = acc (fp32) ; EPI 1: C = X + acc (fp32) ; EPI 2: silu(X)*acc
// OUTHL: write result as bf16 hi/lo to Oh/Ol instead of fp32 C.
// NBs = B row stride (may exceed N for padded LM head); C/X stride = N.
// NOTE: fp32 stores use scalar path when N is odd (LM head) — alignment.
template<int EPI, bool OUTHL>
__global__ __launch_bounds__(256, 2)
void gemm_bf(const uint16_t* __restrict__ Ah, const uint16_t* __restrict__ Al,
             const uint16_t* __restrict__ Bh, const uint16_t* __restrict__ Bl,
             const float* __restrict__ X, float* __restrict__ C,
             uint16_t* __restrict__ Oh, uint16_t* __restrict__ Ol,
             int M, int N, int NBs, int K) {
    extern __shared__ __align__(16) char sm[];
    const uint32_t sb = (uint32_t)__cvta_generic_to_shared(sm);

    const int tid  = threadIdx.x;
    const int lane = tid & 31;
    const int warp = tid >> 5;
    const int wm = warp & 3;        // 0..3
    const int wn = warp >> 2;       // 0..1
    const int lq = lane >> 2;       // 0..7
    const int lr = lane & 3;        // 0..3
    const int m0 = blockIdx.y * BM;
    const int n0 = blockIdx.x * BN;

    float c[2][8][4];
    #pragma unroll
    for (int i = 0; i < 2; i++)
        #pragma unroll
        for (int j = 0; j < 8; j++)
            #pragma unroll
            for (int k = 0; k < 4; k++) c[i][j][k] = 0.0f;

    // per-thread load slots (256 threads):
    // A: 128 rows x 2 chunks of 8 bf16 : m = tid>>1, kc = (tid&1)*8
    // B: 16 rows x 16 chunks           : k = tid>>4, nc = (tid&15)*8
    const int am = tid >> 1;
    const int ak = (tid & 1) * 8;
    const int bk = tid >> 4;
    const int bn = (tid & 15) * 8;
    const uint32_t a_dst = a_off(am, ak);
    const uint32_t b_dst = b_off(bk, bn);

    auto issue = [&](int kt) {
        const int kbase = kt * BK;
        const uint32_t stg = sb + (uint32_t)(kt & 3) * (uint32_t)STAGE_BYTES;
        const uint16_t* sa = Ah + (size_t)(m0 + am) * K + kbase + ak;
        const uint16_t* sa2 = Al + (size_t)(m0 + am) * K + kbase + ak;
        CPASYNC16(stg + a_dst, sa);
        CPASYNC16(stg + 4096u + a_dst, sa2);
        const uint16_t* sbh = Bh + (size_t)(kbase + bk) * NBs + n0 + bn;
        const uint16_t* sbl = Bl + (size_t)(kbase + bk) * NBs + n0 + bn;
        CPASYNC16(stg + 8192u + b_dst, sbh);
        CPASYNC16(stg + 12288u + b_dst, sbl);
        asm volatile("cp.async.commit_group;" ::: "memory");
    };

    const int lid8 = lane >> 3;      // matrix id 0..3
    const int lrow = lane & 7;       // row within matrix

    auto compute = [&](int buf) {
        const uint32_t ah_base = sb + (uint32_t)buf * (uint32_t)STAGE_BYTES;
        const uint32_t al_base = ah_base + 4096u;
        const uint32_t bh_base = ah_base + 8192u;
        const uint32_t bl_base = ah_base + 12288u;

        uint32_t ah[2][4], al[2][4];
        {
            int m = ((lid8 & 1) << 3) + lrow;
            int k = (lid8 >> 1) << 3;
            #pragma unroll
            for (int mf = 0; mf < 2; mf++) {
                uint32_t off = a_off(wm * 32 + mf * 16 + m, k);
                ldsm4(ah[mf], ah_base + off);
                ldsm4(al[mf], al_base + off);
            }
        }
        #pragma unroll
        for (int h = 0; h < 2; h++) {
            uint32_t bhf[4][2], blf[4][2];
            #pragma unroll
            for (int j = 0; j < 2; j++) {
                int k  = ((lid8 & 1) << 3) + lrow;
                int nb = wn * 8 + h * 4 + j * 2 + (lid8 >> 1);
                uint32_t off = b_off(k, nb << 3);
                uint32_t rr[4];
                ldsm4t(rr, bh_base + off);
                bhf[j * 2][0] = rr[0]; bhf[j * 2][1] = rr[1];
                bhf[j * 2 + 1][0] = rr[2]; bhf[j * 2 + 1][1] = rr[3];
                ldsm4t(rr, bl_base + off);
                blf[j * 2][0] = rr[0]; blf[j * 2][1] = rr[1];
                blf[j * 2 + 1][0] = rr[2]; blf[j * 2 + 1][1] = rr[3];
            }
            #pragma unroll
            for (int mf = 0; mf < 2; mf++)
                #pragma unroll
                for (int j = 0; j < 4; j++) {
                    int nf = h * 4 + j;
                    MMA_BF16(c[mf][nf], ah[mf], bhf[j][0], bhf[j][1]);
                    MMA_BF16(c[mf][nf], ah[mf], blf[j][0], blf[j][1]);
                    MMA_BF16(c[mf][nf], al[mf], bhf[j][0], bhf[j][1]);
                }
        }
    };

    // ---- main loop: 4-stage cp.async pipeline ----
    const int ntk = K / BK;
    issue(0); issue(1); issue(2);
    for (int kt = 0; kt < ntk; kt++) {
        asm volatile("cp.async.wait_group 2;" ::: "memory");
        __syncthreads();
        compute(kt & 3);
        if (kt + 3 < ntk) issue(kt + 3);
        else asm volatile("cp.async.commit_group;" ::: "memory");
    }

    // ---- epilogue ----
    const bool evenN = ((N & 1) == 0);
    #pragma unroll
    for (int mf = 0; mf < 2; mf++) {
        int r0 = m0 + wm * 32 + mf * 16 + lq;
        int r1 = r0 + 8;
        #pragma unroll
        for (int nf = 0; nf < 8; nf++) {
            int col = n0 + wn * 64 + nf * 8 + 2 * lr;
            size_t o0 = (size_t)r0 * N + col;
            size_t o1 = (size_t)r1 * N + col;
            float2 v0 = make_float2(c[mf][nf][0], c[mf][nf][1]);
            float2 v1 = make_float2(c[mf][nf][2], c[mf][nf][3]);
            if (col + 2 <= N) {
                if (EPI == 1) {
                    float2 x0 = *(const float2*)(X + o0);
                    float2 x1 = *(const float2*)(X + o1);
                    v0.x += x0.x; v0.y += x0.y; v1.x += x1.x; v1.y += x1.y;
                } else if (EPI == 2) {
                    float2 x0 = *(const float2*)(X + o0);
                    float2 x1 = *(const float2*)(X + o1);
                    v0.x *= x0.x / (1.0f + __expf(-x0.x));
                    v0.y *= x0.y / (1.0f + __expf(-x0.y));
                    v1.x *= x1.x / (1.0f + __expf(-x1.x));
                    v1.y *= x1.y / (1.0f + __expf(-x1.y));
                }
                if (OUTHL) {
                    uint32_t h0, l0, h1, l1;
                    split2(v0.x, v0.y, h0, l0);
                    split2(v1.x, v1.y, h1, l1);
                    *(uint32_t*)(Oh + o0) = h0;
                    *(uint32_t*)(Ol + o0) = l0;
                    *(uint32_t*)(Oh + o1) = h1;
                    *(uint32_t*)(Ol + o1) = l1;
                } else if (evenN) {
                    *(float2*)(C + o0) = v0;
                    *(float2*)(C + o1) = v1;
                } else {
                    // odd N (LM head): row base parity varies -> scalar stores
                    C[o0] = v0.x; C[o0 + 1] = v0.y;
                    C[o1] = v1.x; C[o1 + 1] = v1.y;
                }
            } else if (col < N) {
                // scalar tail (LM head last column block)
                float a0 = v0.x, a1 = v1.x;
                if (EPI == 1) { a0 += X[o0]; a1 += X[o1]; }
                else if (EPI == 2) {
                    float x0 = X[o0], x1 = X[o1];
                    a0 *= x0 / (1.0f + __expf(-x0));
                    a1 *= x1 / (1.0f + __expf(-x1));
                }
                C[o0] = a0; C[o1] = a1;
            }
        }
    }
}

// ---------------- flash attention v2 (causal, fp32, 2 threads/row) --------
// grid (NB_*NH, NS/64), block 128; output written as bf16 hi/lo.
__global__ __launch_bounds__(128)
void attn_kernel(const float* __restrict__ qkv,
                 uint16_t* __restrict__ yh, uint16_t* __restrict__ yl) {
    const int bh = blockIdx.x;
    const int b  = bh >> 4;
    const int hd = bh & 15;
    const int qg = blockIdx.y;            // 0..15
    const int tid = threadIdx.x;          // 0..127
    const int row = tid >> 1;             // 0..63
    const int half = tid & 1;
    const int qrow = qg * 64 + row;
    const int doff = half * 4;

    const float* qptr = qkv + ((size_t)(b * NS + qrow) * (3 * ND)) + hd * NDH;
    float4 q[8];
    #pragma unroll
    for (int i = 0; i < 8; i++)
        q[i] = *(const float4*)(qptr + i * 8 + doff);

    float4 o[8];
    #pragma unroll
    for (int i = 0; i < 8; i++) o[i] = make_float4(0.f, 0.f, 0.f, 0.f);
    float m = -1e30f, l = 0.0f;

    __shared__ float ksm[64][64];
    __shared__ float vsm[64][64];

    const int ntiles = qg + 1;
    for (int kt = 0; kt < ntiles; kt++) {
        const int kbase = kt * 64;
        #pragma unroll
        for (int i = 0; i < 8; i++) {
            int li = tid + i * 128;
            int r  = li >> 4;
            int c4 = (li & 15) * 4;
            const float* base = qkv + ((size_t)(b * NS + kbase + r) * (3 * ND))
                                + hd * NDH + c4;
            *(float4*)&ksm[r][c4] = *(const float4*)(base + ND);
            *(float4*)&vsm[r][c4] = *(const float4*)(base + 2 * ND);
        }
        __syncthreads();

        #pragma unroll 1
        for (int jt = 0; jt < 4; jt++) {
            float s[16];
            #pragma unroll
            for (int j = 0; j < 16; j++) {
                int jr = jt * 16 + j;
                float a = 0.0f;
                #pragma unroll
                for (int i = 0; i < 8; i++) {
                    float4 kv = *(const float4*)&ksm[jr][i * 8 + doff];
                    a += q[i].x * kv.x + q[i].y * kv.y
                       + q[i].z * kv.z + q[i].w * kv.w;
                }
                a += __shfl_xor_sync(0xFFFFFFFFu, a, 1);
                int key = kbase + jr;
                s[j] = (key <= qrow) ? a * 0.125f : -1e30f;
            }
            float tm = s[0];
            #pragma unroll
            for (int j = 1; j < 16; j++) tm = fmaxf(tm, s[j]);
            float mnew = fmaxf(m, tm);
            float corr = __expf(m - mnew);
            float psum = 0.0f;
            #pragma unroll
            for (int j = 0; j < 16; j++) {
                s[j] = __expf(s[j] - mnew);
                psum += s[j];
            }
            l = l * corr + psum;
            m = mnew;
            #pragma unroll
            for (int i = 0; i < 8; i++) {
                o[i].x *= corr; o[i].y *= corr; o[i].z *= corr; o[i].w *= corr;
            }
            #pragma unroll
            for (int j = 0; j < 16; j++) {
                float p = s[j];
                int jr = jt * 16 + j;
                #pragma unroll
                for (int i = 0; i < 8; i++) {
                    float4 vv = *(const float4*)&vsm[jr][i * 8 + doff];
                    o[i].x += p * vv.x; o[i].y += p * vv.y;
                    o[i].z += p * vv.z; o[i].w += p * vv.w;
                }
            }
        }
        __syncthreads();
    }

    float inv = 1.0f / l;
    size_t base = (size_t)(b * NS + qrow) * ND + hd * NDH;
    #pragma unroll
    for (int i = 0; i < 8; i++) {
        float4 st;
        st.x = o[i].x * inv; st.y = o[i].y * inv;
        st.z = o[i].z * inv; st.w = o[i].w * inv;
        uint2 hi, lo;
        split4(st, hi, lo);
        size_t eo = base + i * 8 + doff;
        *(uint2*)(yh + eo) = hi;
        *(uint2*)(yl + eo) = lo;
    }
}

// ---------------- launch ----------------
extern "C" void kernel_launch(void* const* d_in, const int* in_sizes, int n_in,
                              void* d_out, int out_size) {
    const int*   idx   = (const int*)  d_in[0];
    const float* wte   = (const float*)d_in[1];
    const float* wpe   = (const float*)d_in[2];
    const float* g1    = (const float*)d_in[3];
    const float* Wqkv  = (const float*)d_in[4];
    const float* Wproj = (const float*)d_in[5];
    const float* g2    = (const float*)d_in[6];
    const float* Wg    = (const float*)d_in[7];
    const float* Wu    = (const float*)d_in[8];
    const float* Wd    = (const float*)d_in[9];
    const float* gf    = (const float*)d_in[10];
    const float* Wlm   = (const float*)d_in[11];
    float* out = (float*)d_out;

    float *px, *pqkv, *pgate;
    uint16_t *phh, *phl, *pyh, *pyl, *psh, *psl;
    uint16_t *wqh, *wql, *wph, *wpl, *wgh, *wgl, *wuh, *wul, *wdh, *wdl, *wlh, *wll;
    cudaGetSymbolAddress((void**)&px,    g_x);
    cudaGetSymbolAddress((void**)&pqkv,  g_qkv);
    cudaGetSymbolAddress((void**)&pgate, g_gate);
    cudaGetSymbolAddress((void**)&phh,   g_hh);
    cudaGetSymbolAddress((void**)&phl,   g_hl);
    cudaGetSymbolAddress((void**)&pyh,   g_yh);
    cudaGetSymbolAddress((void**)&pyl,   g_yl);
    cudaGetSymbolAddress((void**)&psh,   g_sh);
    cudaGetSymbolAddress((void**)&psl,   g_sl);
    cudaGetSymbolAddress((void**)&wqh,   g_wqkv_h);
    cudaGetSymbolAddress((void**)&wql,   g_wqkv_l);
    cudaGetSymbolAddress((void**)&wph,   g_wproj_h);
    cudaGetSymbolAddress((void**)&wpl,   g_wproj_l);
    cudaGetSymbolAddress((void**)&wgh,   g_wg_h);
    cudaGetSymbolAddress((void**)&wgl,   g_wg_l);
    cudaGetSymbolAddress((void**)&wuh,   g_wu_h);
    cudaGetSymbolAddress((void**)&wul,   g_wu_l);
    cudaGetSymbolAddress((void**)&wdh,   g_wd_h);
    cudaGetSymbolAddress((void**)&wdl,   g_wd_l);
    cudaGetSymbolAddress((void**)&wlh,   g_wlm_h);
    cudaGetSymbolAddress((void**)&wll,   g_wlm_l);

    cudaFuncSetAttribute(gemm_bf<0, false>,
        cudaFuncAttributeMaxDynamicSharedMemorySize, SMEM_BYTES);
    cudaFuncSetAttribute(gemm_bf<1, false>,
        cudaFuncAttributeMaxDynamicSharedMemorySize, SMEM_BYTES);
    cudaFuncSetAttribute(gemm_bf<2, true>,
        cudaFuncAttributeMaxDynamicSharedMemorySize, SMEM_BYTES);

    // ---- weight split (runs each call) ----
    {
        int n4;
        n4 = NL * ND * 3 * ND / 4;
        wsplit_kernel<<<(n4 + 255) / 256, 256>>>(Wqkv, wqh, wql, n4);
        n4 = NL * ND * ND / 4;
        wsplit_kernel<<<(n4 + 255) / 256, 256>>>(Wproj, wph, wpl, n4);
        n4 = NL * ND * NHID / 4;
        wsplit_kernel<<<(n4 + 255) / 256, 256>>>(Wg, wgh, wgl, n4);
        wsplit_kernel<<<(n4 + 255) / 256, 256>>>(Wu, wuh, wul, n4);
        n4 = NL * NHID * ND / 4;
        wsplit_kernel<<<(n4 + 255) / 256, 256>>>(Wd, wdh, wdl, n4);
        wsplit_pad_kernel<<<dim3((NVP + 255) / 256, ND), 256>>>(Wlm, wlh, wll);
    }

    embed_kernel<<<MTOK, 256>>>(idx, wte, wpe, px);

    for (int l = 0; l < NL; l++) {
        rmsnorm_hl_kernel<<<MTOK, 256>>>(px, g1 + (size_t)l * ND, phh, phl);
        gemm_bf<0, false><<<dim3(3 * ND / BN, MTOK / BM), 256, SMEM_BYTES>>>(
            phh, phl, wqh + (size_t)l * ND * 3 * ND, wql + (size_t)l * ND * 3 * ND,
            nullptr, pqkv, nullptr, nullptr, MTOK, 3 * ND, 3 * ND, ND);
        attn_kernel<<<dim3(NB_ * NH, NS / 64), 128>>>(pqkv, pyh, pyl);
        gemm_bf<1, false><<<dim3(ND / BN, MTOK / BM), 256, SMEM_BYTES>>>(
            pyh, pyl, wph + (size_t)l * ND * ND, wpl + (size_t)l * ND * ND,
            px, px, nullptr, nullptr, MTOK, ND, ND, ND);
        rmsnorm_hl_kernel<<<MTOK, 256>>>(px, g2 + (size_t)l * ND, phh, phl);
        gemm_bf<0, false><<<dim3(NHID / BN, MTOK / BM), 256, SMEM_BYTES>>>(
            phh, phl, wgh + (size_t)l * ND * NHID, wgl + (size_t)l * ND * NHID,
            nullptr, pgate, nullptr, nullptr, MTOK, NHID, NHID, ND);
        gemm_bf<2, true><<<dim3(NHID / BN, MTOK / BM), 256, SMEM_BYTES>>>(
            phh, phl, wuh + (size_t)l * ND * NHID, wul + (size_t)l * ND * NHID,
            pgate, nullptr, psh, psl, MTOK, NHID, NHID, ND);
        gemm_bf<1, false><<<dim3(ND / BN, MTOK / BM), 256, SMEM_BYTES>>>(
            psh, psl, wdh + (size_t)l * NHID * ND, wdl + (size_t)l * NHID * ND,
            px, px, nullptr, nullptr, MTOK, ND, ND, NHID);
    }

    rmsnorm_hl_kernel<<<MTOK, 256>>>(px, gf, phh, phl);
    gemm_bf<0, false><<<dim3(NVP / BN, MTOK / BM), 256, SMEM_BYTES>>>(
        phh, phl, wlh, wll, nullptr, out, nullptr, nullptr, MTOK, NV, NVP, ND);
}